// round 10
// baseline (speedup 1.0000x reference)
#include <cuda_runtime.h>
#include <cstdint>

// ActionSmoothingLoss: segmented log-softmax KL
// NVEC = (3,3,4,25,25,8), A = 68, W = 524288
// TMA bulk + mbarrier: TWO interleaved half-block pipelines, 6-slot ring.

#define A_DIM        68
#define NSEG         6
#define BLOCK        256
#define GRP          128                       // threads per group
#define RPS          128                       // rows per stage
#define STAGE_FLOATS (RPS * A_DIM)             // 8704
#define STAGE_BYTES  (STAGE_FLOATS * 4)        // 34816
#define SLOTS_PER_P  3
#define NSLOTS       6
#define GRID_MAX     148

__device__ double g_part[GRID_MAX];
__device__ unsigned int g_count = 0;           // returns to 0 each call

#define SEG_OF(k) ((k) < 3 ? 0 : (k) < 6 ? 1 : (k) < 10 ? 2 : (k) < 35 ? 3 : (k) < 60 ? 4 : 5)

__device__ __forceinline__ uint32_t s2u(const void* p) {
    return (uint32_t)__cvta_generic_to_shared(p);
}
__device__ __forceinline__ void mbar_init(uint32_t a, uint32_t cnt) {
    asm volatile("mbarrier.init.shared.b64 [%0], %1;" :: "r"(a), "r"(cnt) : "memory");
}
__device__ __forceinline__ void mbar_expect_tx(uint32_t a, uint32_t bytes) {
    asm volatile("mbarrier.arrive.expect_tx.shared.b64 _, [%0], %1;" :: "r"(a), "r"(bytes) : "memory");
}
__device__ __forceinline__ void mbar_arrive(uint32_t a) {
    asm volatile("mbarrier.arrive.shared.b64 _, [%0];" :: "r"(a) : "memory");
}
__device__ __forceinline__ void mbar_wait(uint32_t a, uint32_t ph) {
    uint32_t done;
    do {
        asm volatile("{\n\t.reg .pred p;\n\t"
                     "mbarrier.try_wait.parity.acquire.cta.shared::cta.b64 p, [%1], %2, 0x989680;\n\t"
                     "selp.b32 %0, 1, 0, p;\n\t}"
                     : "=r"(done) : "r"(a), "r"(ph) : "memory");
    } while (!done);
}
__device__ __forceinline__ void bulk_g2s(uint32_t dst, const void* src,
                                         uint32_t bytes, uint32_t mbar) {
    asm volatile("cp.async.bulk.shared::cluster.global.mbarrier::complete_tx::bytes "
                 "[%0], [%1], %2, [%3];"
                 :: "r"(dst), "l"(src), "r"(bytes), "r"(mbar) : "memory");
}

extern __shared__ float dynsmem[];             // NSLOTS * STAGE_FLOATS

__global__ void __launch_bounds__(BLOCK, 1) asl_kernel(
    const float* __restrict__ cur,
    const float* __restrict__ prev,
    float* __restrict__ out,
    int W, int nstages_total, int nblocks)
{
    __shared__ __align__(8) uint64_t full_bar[NSLOTS];
    __shared__ __align__(8) uint64_t empty_bar[NSLOTS];
    __shared__ float xs[A_DIM];
    __shared__ double wred[BLOCK / 32];
    __shared__ bool is_last;

    const int tid  = threadIdx.x;
    const int warp = tid >> 5;
    const int lane = tid & 31;
    const int p    = tid >> 7;                 // pipeline group 0/1
    const int gt   = tid & (GRP - 1);          // thread id within group

    // --- init barriers + current_action log-softmax ---
    if (tid < A_DIM) xs[tid] = cur[tid];
    if (tid == 0) {
        #pragma unroll
        for (int s = 0; s < NSLOTS; s++) {
            mbar_init(s2u(&full_bar[s]), 1);
            mbar_init(s2u(&empty_bar[s]), GRP);
        }
    }
    __syncthreads();
    asm volatile("fence.proxy.async.shared::cta;" ::: "memory");
    if (tid < NSEG) {
        const int off[NSEG] = {0, 3, 6, 10, 35, 60};
        const int sz[NSEG]  = {3, 3, 4, 25, 25, 8};
        const int o = off[tid], n = sz[tid];
        float s = 0.f;
        for (int i = 0; i < n; i++) s += __expf(xs[o + i]);
        const float L = __logf(s);
        for (int i = 0; i < n; i++) xs[o + i] -= L;
    }
    __syncthreads();

    // block's local iterations j handle global stage (blockIdx.x + j*nblocks);
    // group p owns local iterations j = p, p+2, p+4, ...
    int myiters = 0;
    if (blockIdx.x < nstages_total)
        myiters = (nstages_total - 1 - blockIdx.x) / nblocks + 1;
    const int mcount = (myiters - p + 1) / 2;   // iterations for this group

    const char* gbase = reinterpret_cast<const char*>(prev);

    auto issue = [&](int m) {                  // group producer only (gt==0)
        const int j = p + 2 * m;
        const int stage = blockIdx.x + j * nblocks;
        const int slot  = p * SLOTS_PER_P + (m % SLOTS_PER_P);
        const size_t row0 = (size_t)stage * RPS;
        int rows = W - (int)row0; if (rows > RPS) rows = RPS;
        const uint32_t bytes = (uint32_t)rows * (A_DIM * 4);
        const uint32_t fb = s2u(&full_bar[slot]);
        mbar_expect_tx(fb, bytes);
        bulk_g2s(s2u(dynsmem + (size_t)slot * STAGE_FLOATS),
                 gbase + row0 * (A_DIM * 4), bytes, fb);
    };

    // prologue: each producer fills its 3 slots
    if (gt == 0) {
        const int np = mcount < SLOTS_PER_P ? mcount : SLOTS_PER_P;
        for (int m = 0; m < np; m++) issue(m);
    }

    double acc_d = 0.0;

    for (int m = 0; m < mcount; m++) {
        const int j    = p + 2 * m;
        const int slot = p * SLOTS_PER_P + (m % SLOTS_PER_P);
        const uint32_t ph = (uint32_t)((m / SLOTS_PER_P) & 1);
        mbar_wait(s2u(&full_bar[slot]), ph);

        // --- compute: one row per group thread, 17 x LDS.128 ---
        const int stage = blockIdx.x + j * nblocks;
        const int w = stage * RPS + gt;
        if (w < W) {
            const float4* row = reinterpret_cast<const float4*>(
                dynsmem + (size_t)slot * STAGE_FLOATS + gt * A_DIM);
            float s[NSEG] = {0,0,0,0,0,0};
            float a[NSEG] = {0,0,0,0,0,0};
            #pragma unroll
            for (int i = 0; i < 17; i++) {
                const float4 v = row[i];
                const float vv[4] = {v.x, v.y, v.z, v.w};
                #pragma unroll
                for (int k2 = 0; k2 < 4; k2++) {
                    const int idx = 4 * i + k2;
                    const int jj = SEG_OF(idx);          // compile-time
                    const float r = vv[k2];
                    const float e = __expf(r);
                    s[jj] += e;
                    a[jj] = fmaf(e, r - xs[idx], a[jj]);
                }
            }
            const float invn[NSEG] = {1.f/3.f, 1.f/3.f, 1.f/4.f, 1.f/25.f, 1.f/25.f, 1.f/8.f};
            float row_loss = 0.f;
            #pragma unroll
            for (int jj = 0; jj < NSEG; jj++)
                row_loss += invn[jj] * (__fdividef(a[jj], s[jj]) - __logf(s[jj]));
            acc_d += (double)row_loss;
        }

        mbar_arrive(s2u(&empty_bar[slot]));

        // group producer: refill this slot once group is done with it
        if (gt == 0 && m + SLOTS_PER_P < mcount) {
            mbar_wait(s2u(&empty_bar[slot]), ph);
            issue(m + SLOTS_PER_P);
        }
    }

    __syncthreads();

    // --- block reduction (double), deterministic ---
    double d = acc_d;
    #pragma unroll
    for (int st = 16; st > 0; st >>= 1)
        d += __shfl_down_sync(0xFFFFFFFFu, d, st);
    if (lane == 0) wred[warp] = d;
    __syncthreads();
    if (tid == 0) {
        double b = 0.0;
        #pragma unroll
        for (int k = 0; k < BLOCK / 32; k++) b += wred[k];
        g_part[blockIdx.x] = b;
        __threadfence();
        unsigned int t = atomicAdd(&g_count, 1u);
        is_last = (t == (unsigned int)(nblocks - 1));
    }
    __syncthreads();

    if (is_last) {
        double a2 = 0.0;
        for (int k = tid; k < nblocks; k += BLOCK) a2 += g_part[k];
        #pragma unroll
        for (int st = 16; st > 0; st >>= 1)
            a2 += __shfl_down_sync(0xFFFFFFFFu, a2, st);
        if (lane == 0) wred[warp] = a2;
        __syncthreads();
        if (tid == 0) {
            double tot = 0.0;
            #pragma unroll
            for (int k = 0; k < BLOCK / 32; k++) tot += wred[k];
            out[0] = (float)(tot / (double)W);
            g_count = 0;
        }
    }
}

extern "C" void kernel_launch(void* const* d_in, const int* in_sizes, int n_in,
                              void* d_out, int out_size)
{
    const float* cur  = (const float*)d_in[0];   // [68]
    const float* prev = (const float*)d_in[1];   // [W, 68]
    const int W = in_sizes[1] / A_DIM;
    const int nstages_total = (W + RPS - 1) / RPS;

    int nblocks = GRID_MAX;
    if (nblocks > (nstages_total + 1) / 2) nblocks = (nstages_total + 1) / 2;

    const int dyn = NSLOTS * STAGE_BYTES;        // 208896 B
    static int configured = 0;
    if (!configured) {
        cudaFuncSetAttribute(asl_kernel,
                             cudaFuncAttributeMaxDynamicSharedMemorySize, dyn);
        configured = 1;
    }

    asl_kernel<<<nblocks, BLOCK, dyn>>>(cur, prev, (float*)d_out,
                                        W, nstages_total, nblocks);
}